// round 13
// baseline (speedup 1.0000x reference)
#include <cuda_runtime.h>

// d_w(theta) = A_w cos(theta) + B_w sin(theta),
//   A_w = cos(alpha_w)cos(beta_w), B_w = -sin(beta_w)  (Rz param is dead).
// Phase-folded: d_w = R_w cos(theta - phi_w). With W'_k = W_k * prod_{j<=k} R_j:
//   out = c0*(W0' + c1*(W1' + c2*(W2' + c3*W3'))),  c_w = __cosf(theta_w - phi_w)
// => 1 MUFU + 1 FADD + ~1 FMA per pixel. ALL constant work (phi + cumulative W')
// lives in the 4-thread fold; main threads read 2 float4 from smem, nothing else.

__device__ __forceinline__ float fast_atan2f(float y, float x) {
    // Branch-free atan2, |err| ~ 1e-5 rad.
    float ax = fabsf(x), ay = fabsf(y);
    float mn = fminf(ax, ay), mx = fmaxf(ax, ay);
    float r  = __fdividef(mn, mx);
    float s  = r * r;
    float p = fmaf(s, fmaf(s, fmaf(s, fmaf(s, 0.0208351f, -0.0851330f),
                                   0.1801410f), -0.3302995f), 0.9998660f) * r;
    p = (ay > ax) ? (1.5707963f - p) : p;
    p = (x < 0.0f) ? (3.1415927f - p) : p;
    return copysignf(p, y);
}

__device__ __forceinline__ float patch_ev(float t0, float t1, float t2, float t3,
                                          float4 P, float4 Wf) {
    float c0 = __cosf(t0 - P.x);
    float c1 = __cosf(t1 - P.y);
    float c2 = __cosf(t2 - P.z);
    float c3 = __cosf(t3 - P.w);
    return c0 * fmaf(c1, fmaf(c2, fmaf(c3, Wf.w, Wf.z), Wf.y), Wf.x);
}

// One thread computes 2 horizontally-adjacent 2x2 patches.
// Threads: 8192 * 14 * 7 = 802816 = 3136 * 256 (exact, no bounds check).
__global__ void __launch_bounds__(256, 8)
quanv_kernel(const float* __restrict__ x, const float* __restrict__ params,
             const float* __restrict__ W, float* __restrict__ out) {
    __shared__ __align__(16) float sqc[8];   // phi0..3, W'0..3

    int t  = blockIdx.x * 256 + threadIdx.x;
    int jj = t % 7;          // pair-of-patches column (j = 2jj, 2jj+1)
    int bi = t / 7;          // b*14 + i
    int i  = bi % 14;        // patch row
    int b  = bi / 14;        // image

    // Front-batch the streaming loads: in flight during the fold below.
    const float4* xr = reinterpret_cast<const float4*>(x);
    int o0 = b * 196 + i * 14 + jj;
    float4 r0 = xr[o0];       // row 2i
    float4 r1 = xr[o0 + 7];   // row 2i+1

    // Fold on threads 0-3 (branch-free, intrinsics only, ~40 instrs, hidden
    // under the x-load latency). Each fold thread redundantly computes all four
    // R_k so it can form its own prefix product -> single barrier, no chain.
    if (threadIdx.x < 4) {
        int w = threadIdx.x;
        float a  = params[3 * w + 0];
        float bb = params[3 * w + 1];
        float A = __cosf(a) * __cosf(bb);
        float B = -__sinf(bb);
        sqc[w] = fast_atan2f(B, A);          // phi_w
        float Wp = W[w];
        #pragma unroll
        for (int k = 0; k < 4; k++) {
            float ak = params[3 * k + 0];
            float bk = params[3 * k + 1];
            float Ak = __cosf(ak) * __cosf(bk);
            float Bk = -__sinf(bk);
            float Rk = __fsqrt_rn(fmaf(Ak, Ak, Bk * Bk));
            Wp = (k <= w) ? Wp * Rk : Wp;    // predicated select, no branch
        }
        sqc[4 + w] = Wp;                     // W'_w
    }
    __syncthreads();

    const float4* qc = reinterpret_cast<const float4*>(sqc);
    float4 Pv = qc[0], Wf = qc[1];

    float2 o;
    o.x = patch_ev(r0.x, r0.y, r1.x, r1.y, Pv, Wf);
    o.y = patch_ev(r0.z, r0.w, r1.z, r1.w, Pv, Wf);

    // out (B,196): float2 index b*98 + i*7 + jj (8B aligned)
    reinterpret_cast<float2*>(out)[b * 98 + i * 7 + jj] = o;
}

extern "C" void kernel_launch(void* const* d_in, const int* in_sizes, int n_in,
                              void* d_out, int out_size) {
    const float* x      = (const float*)d_in[0];
    const float* params = (const float*)d_in[1];
    const float* W      = (const float*)d_in[2];
    float* out          = (float*)d_out;

    quanv_kernel<<<3136, 256>>>(x, params, W, out);
}

// round 14
// speedup vs baseline: 1.0258x; 1.0258x over previous
#include <cuda_runtime.h>

// d_w(theta) = A_w cos(theta) + B_w sin(theta),
//   A_w = cos(alpha_w)cos(beta_w), B_w = -sin(beta_w)  (Rz param is dead).
// Entangler: Z_k = prod_{j<=k} d_j  ->  out = d0*(W0 + d1*(W1 + d2*(W2 + d3*W3))).
// Fold = 12 fast MUFU on threads 0-3 (no libm slow path), fully hidden under
// the block's front-batched x loads. Main loop: __sincosf (2 MUFU/pixel).
// Measured best config of the session: kernel 8.128us, DRAM 40%, occ 85%.

__device__ __forceinline__ float patch_ev(float t0, float t1, float t2, float t3,
                                          float4 A, float4 B, float4 Wv) {
    float s, c;
    __sincosf(t0, &s, &c); float d0 = fmaf(A.x, c, B.x * s);
    __sincosf(t1, &s, &c); float d1 = fmaf(A.y, c, B.y * s);
    __sincosf(t2, &s, &c); float d2 = fmaf(A.z, c, B.z * s);
    __sincosf(t3, &s, &c); float d3 = fmaf(A.w, c, B.w * s);
    return d0 * fmaf(d1, fmaf(d2, fmaf(d3, Wv.w, Wv.z), Wv.y), Wv.x);
}

// One thread computes 2 horizontally-adjacent 2x2 patches.
// Threads: 8192 * 14 * 7 = 802816 = 3136 * 256 (exact, no bounds check).
__global__ void __launch_bounds__(256, 8)
quanv_kernel(const float* __restrict__ x, const float* __restrict__ params,
             const float* __restrict__ W, float* __restrict__ out) {
    __shared__ __align__(16) float sqc[12];   // A0..3, B0..3, W0..3

    int t  = blockIdx.x * 256 + threadIdx.x;
    int jj = t % 7;          // pair-of-patches column (j = 2jj, 2jj+1)
    int bi = t / 7;          // b*14 + i
    int i  = bi % 14;        // patch row
    int b  = bi / 14;        // image

    // Front-batch the streaming loads: in flight during the (tiny) fold below.
    const float4* xr = reinterpret_cast<const float4*>(x);
    int o0 = b * 196 + i * 14 + jj;
    float4 r0 = xr[o0];       // row 2i
    float4 r1 = xr[o0 + 7];   // row 2i+1

    // Trivial fold: fast intrinsics only (~50 cyc), no libm slow path, so the
    // barrier releases as soon as the param L1 loads land.
    if (threadIdx.x < 4) {
        int w = threadIdx.x;
        float a  = params[3 * w + 0];
        float bb = params[3 * w + 1];
        sqc[w]     = __cosf(a) * __cosf(bb);   // A_w
        sqc[4 + w] = -__sinf(bb);              // B_w
        sqc[8 + w] = W[w];
    }
    __syncthreads();

    const float4* qc = reinterpret_cast<const float4*>(sqc);
    float4 Av = qc[0], Bv = qc[1], Wv = qc[2];

    float2 o;
    o.x = patch_ev(r0.x, r0.y, r1.x, r1.y, Av, Bv, Wv);
    o.y = patch_ev(r0.z, r0.w, r1.z, r1.w, Av, Bv, Wv);

    // out (B,196): float2 index b*98 + i*7 + jj (8B aligned)
    reinterpret_cast<float2*>(out)[b * 98 + i * 7 + jj] = o;
}

extern "C" void kernel_launch(void* const* d_in, const int* in_sizes, int n_in,
                              void* d_out, int out_size) {
    const float* x      = (const float*)d_in[0];
    const float* params = (const float*)d_in[1];
    const float* W      = (const float*)d_in[2];
    float* out          = (float*)d_out;

    quanv_kernel<<<3136, 256>>>(x, params, W, out);
}

// round 15
// speedup vs baseline: 1.0296x; 1.0037x over previous
#include <cuda_runtime.h>

// d_w(theta) = A_w cos(theta) + B_w sin(theta),
//   A_w = cos(alpha_w)cos(beta_w), B_w = -sin(beta_w)  (Rz param is dead).
// Entangler: Z_k = prod_{j<=k} d_j  ->  out = d0*(W0 + d1*(W1 + d2*(W2 + d3*W3))).
// Fold = 12 fast MUFU on threads 0-3 (no libm slow path), fully hidden under
// the block's front-batched x loads. Main loop: __sincosf (2 MUFU/pixel).
// Same thread mapping as the 8.128us record config; block=512 halves the
// number of fold/barrier instances (A/B test vs block=256).

__device__ __forceinline__ float patch_ev(float t0, float t1, float t2, float t3,
                                          float4 A, float4 B, float4 Wv) {
    float s, c;
    __sincosf(t0, &s, &c); float d0 = fmaf(A.x, c, B.x * s);
    __sincosf(t1, &s, &c); float d1 = fmaf(A.y, c, B.y * s);
    __sincosf(t2, &s, &c); float d2 = fmaf(A.z, c, B.z * s);
    __sincosf(t3, &s, &c); float d3 = fmaf(A.w, c, B.w * s);
    return d0 * fmaf(d1, fmaf(d2, fmaf(d3, Wv.w, Wv.z), Wv.y), Wv.x);
}

// One thread computes 2 horizontally-adjacent 2x2 patches.
// Threads: 8192 * 14 * 7 = 802816 = 1568 * 512 (exact, no bounds check).
__global__ void __launch_bounds__(512, 4)
quanv_kernel(const float* __restrict__ x, const float* __restrict__ params,
             const float* __restrict__ W, float* __restrict__ out) {
    __shared__ __align__(16) float sqc[12];   // A0..3, B0..3, W0..3

    int t  = blockIdx.x * 512 + threadIdx.x;
    int jj = t % 7;          // pair-of-patches column (j = 2jj, 2jj+1)
    int bi = t / 7;          // b*14 + i
    int i  = bi % 14;        // patch row
    int b  = bi / 14;        // image

    // Front-batch the streaming loads: in flight during the (tiny) fold below.
    const float4* xr = reinterpret_cast<const float4*>(x);
    int o0 = b * 196 + i * 14 + jj;
    float4 r0 = xr[o0];       // row 2i
    float4 r1 = xr[o0 + 7];   // row 2i+1

    // Trivial fold: fast intrinsics only (~50 cyc), no libm slow path, so the
    // barrier releases as soon as the param L1 loads land.
    if (threadIdx.x < 4) {
        int w = threadIdx.x;
        float a  = params[3 * w + 0];
        float bb = params[3 * w + 1];
        sqc[w]     = __cosf(a) * __cosf(bb);   // A_w
        sqc[4 + w] = -__sinf(bb);              // B_w
        sqc[8 + w] = W[w];
    }
    __syncthreads();

    const float4* qc = reinterpret_cast<const float4*>(sqc);
    float4 Av = qc[0], Bv = qc[1], Wv = qc[2];

    float2 o;
    o.x = patch_ev(r0.x, r0.y, r1.x, r1.y, Av, Bv, Wv);
    o.y = patch_ev(r0.z, r0.w, r1.z, r1.w, Av, Bv, Wv);

    // out (B,196): float2 index b*98 + i*7 + jj == t (fully coalesced)
    reinterpret_cast<float2*>(out)[b * 98 + i * 7 + jj] = o;
}

extern "C" void kernel_launch(void* const* d_in, const int* in_sizes, int n_in,
                              void* d_out, int out_size) {
    const float* x      = (const float*)d_in[0];
    const float* params = (const float*)d_in[1];
    const float* W      = (const float*)d_in[2];
    float* out          = (float*)d_out;

    quanv_kernel<<<1568, 512>>>(x, params, W, out);
}